// round 13
// baseline (speedup 1.0000x reference)
#include <cuda_runtime.h>

#define B_SZ     1024
#define CH       64
#define NI       100000
#define HIST     50
#define BM       64
#define BN       128
#define NTHREADS 128

__device__ double g_loss;

__global__ void k_zero() { g_loss = 0.0; }

// C[b, n] = sum_k U[uid[b], k] * I[n, k]; fused sum of squares into g_loss.
template<bool ALIGNED>
__global__ __launch_bounds__(NTHREADS)
void k_gemm(const float* __restrict__ user_emb,
            const float* __restrict__ item_emb,
            const int*   __restrict__ uid,
            float*       __restrict__ pref)
{
    __shared__ float Us[CH][BM];   // 16 KB, k-major user tile
    __shared__ float Is[CH][BN];   // 32 KB, k-major item tile (total = 48 KB exactly)

    const int t  = threadIdx.x;
    const int tx = t & 15;         // 0..15 -> 8 cols each
    const int ty = t >> 4;         // 0..7  -> 8 rows each
    const int brow = blockIdx.y * BM;
    const int bcol = blockIdx.x * BN;

    // ---- load user tile (gather rows via uid), store transposed (k-major) ----
    #pragma unroll
    for (int it = 0; it < (BM * CH / 4) / NTHREADS; it++) {   // 8 iters
        int f = t + it * NTHREADS;       // float4 id
        int m = f >> 4;                  // 0..63
        int q = f & 15;                  // float4 within the 64-float row
        int u = __ldg(&uid[brow + m]);
        float4 v = *reinterpret_cast<const float4*>(user_emb + (size_t)u * CH + q * 4);
        Us[q * 4 + 0][m] = v.x;
        Us[q * 4 + 1][m] = v.y;
        Us[q * 4 + 2][m] = v.z;
        Us[q * 4 + 3][m] = v.w;
    }
    // ---- load item tile, store transposed (k-major); zero-fill past NI ----
    #pragma unroll
    for (int it = 0; it < (BN * CH / 4) / NTHREADS; it++) {   // 16 iters
        int f = t + it * NTHREADS;
        int n = f >> 4;                  // 0..127
        int q = f & 15;
        int col = bcol + n;
        float4 v = make_float4(0.f, 0.f, 0.f, 0.f);
        if (col < NI)
            v = *reinterpret_cast<const float4*>(item_emb + (size_t)col * CH + q * 4);
        Is[q * 4 + 0][n] = v.x;
        Is[q * 4 + 1][n] = v.y;
        Is[q * 4 + 2][n] = v.z;
        Is[q * 4 + 3][n] = v.w;
    }
    __syncthreads();

    float acc[8][8];
    #pragma unroll
    for (int i = 0; i < 8; i++)
        #pragma unroll
        for (int j = 0; j < 8; j++) acc[i][j] = 0.f;

    // ---- main K loop: conflict-free float4 smem reads, 64 FFMA per k ----
    #pragma unroll 8
    for (int k = 0; k < CH; k++) {
        float4 a0 = *reinterpret_cast<const float4*>(&Us[k][ty * 8]);
        float4 a1 = *reinterpret_cast<const float4*>(&Us[k][ty * 8 + 4]);
        float4 b0 = *reinterpret_cast<const float4*>(&Is[k][tx * 8]);
        float4 b1 = *reinterpret_cast<const float4*>(&Is[k][tx * 8 + 4]);
        float a[8] = {a0.x, a0.y, a0.z, a0.w, a1.x, a1.y, a1.z, a1.w};
        float b[8] = {b0.x, b0.y, b0.z, b0.w, b1.x, b1.y, b1.z, b1.w};
        #pragma unroll
        for (int i = 0; i < 8; i++)
            #pragma unroll
            for (int j = 0; j < 8; j++)
                acc[i][j] = fmaf(a[i], b[j], acc[i][j]);
    }

    // ---- fused loss partial: sum of squares (zero-padded cols contribute 0) ----
    float ls = 0.f;
    #pragma unroll
    for (int i = 0; i < 8; i++)
        #pragma unroll
        for (int j = 0; j < 8; j++)
            ls = fmaf(acc[i][j], acc[i][j], ls);
    #pragma unroll
    for (int o = 16; o > 0; o >>= 1)
        ls += __shfl_xor_sync(0xffffffffu, ls, o);

    __syncthreads();   // everyone done reading Us/Is -> safe to reuse smem

    float* red = &Us[0][0];
    if ((t & 31) == 0) red[t >> 5] = ls;

    if (ALIGNED) {
        // direct vectorized stores (pref 16B-aligned)
        #pragma unroll
        for (int i = 0; i < 8; i++) {
            int row = brow + ty * 8 + i;
            int col = bcol + tx * 8;
            if (col < NI) {   // NI % 8 == 0 so whole 8-group is valid together
                float* p = pref + (size_t)row * NI + col;
                *reinterpret_cast<float4*>(p)     = make_float4(acc[i][0], acc[i][1], acc[i][2], acc[i][3]);
                *reinterpret_cast<float4*>(p + 4) = make_float4(acc[i][4], acc[i][5], acc[i][6], acc[i][7]);
            }
        }
        __syncthreads();
        if (t == 0) atomicAdd(&g_loss, (double)(red[0] + red[1] + red[2] + red[3]));
    } else {
        // pref is off-by-one-float (loss at d_out[0]) -> stage tile in smem,
        // then coalesced scalar stores.
        float* stage = &Is[0][0];            // 64*128 floats = 32 KB
        #pragma unroll
        for (int i = 0; i < 8; i++) {
            float* s = &stage[(ty * 8 + i) * BN + tx * 8];
            *reinterpret_cast<float4*>(s)     = make_float4(acc[i][0], acc[i][1], acc[i][2], acc[i][3]);
            *reinterpret_cast<float4*>(s + 4) = make_float4(acc[i][4], acc[i][5], acc[i][6], acc[i][7]);
        }
        __syncthreads();
        if (t == 0) atomicAdd(&g_loss, (double)(red[0] + red[1] + red[2] + red[3]));
        #pragma unroll 4
        for (int idx = t; idx < BM * BN; idx += NTHREADS) {
            int r = idx >> 7;          // / BN
            int c = idx & (BN - 1);
            int col = bcol + c;
            if (col < NI)
                pref[(size_t)(brow + r) * NI + col] = stage[idx];
        }
    }
}

// Positive-mask correction: loss += sum over UNIQUE (row, seq[row][j]) of (1 - 2*s).
// Dedup matches jnp mask-scatter semantics (duplicates set the same bit once).
__global__ void k_pos(const int* __restrict__ seq, const float* __restrict__ pref)
{
    __shared__ int   s[HIST];
    __shared__ float ws[2];
    const int row = blockIdx.x;
    const int t   = threadIdx.x;     // 64 threads
    if (t < HIST) s[t] = seq[row * HIST + t];
    __syncthreads();

    float c = 0.f;
    if (t < HIST) {
        int v = s[t];
        bool dup = false;
        for (int j = 0; j < t; j++) dup |= (s[j] == v);
        if (!dup)
            c = 1.0f - 2.0f * pref[(size_t)row * NI + v];
    }
    #pragma unroll
    for (int o = 16; o > 0; o >>= 1)
        c += __shfl_xor_sync(0xffffffffu, c, o);
    if ((t & 31) == 0) ws[t >> 5] = c;
    __syncthreads();
    if (t == 0) atomicAdd(&g_loss, (double)(ws[0] + ws[1]));
}

__global__ void k_fin(float* loss_out) { *loss_out = (float)g_loss; }

extern "C" void kernel_launch(void* const* d_in, const int* in_sizes, int n_in,
                              void* d_out, int out_size)
{
    const float* user_emb = (const float*)d_in[0];
    const float* item_emb = (const float*)d_in[1];
    const int*   uid      = (const int*)d_in[2];
    const int*   seq      = (const int*)d_in[3];
    float* out = (float*)d_out;

    const long long full = (long long)B_SZ * NI;   // 102,400,000
    float* pref;
    float* loss_ptr = nullptr;
    bool aligned;

    if ((long long)out_size == full + 1) {
        // tuple order (loss, pref_score): scalar first, matrix after.
        loss_ptr = out;
        pref     = out + 1;
        aligned  = false;
    } else {
        pref    = out;
        aligned = true;
        if ((long long)out_size >= full + 1) loss_ptr = out + full;
    }

    dim3 grid((NI + BN - 1) / BN, B_SZ / BM);   // 782 x 16
    k_zero<<<1, 1>>>();
    if (aligned) k_gemm<true ><<<grid, NTHREADS>>>(user_emb, item_emb, uid, pref);
    else         k_gemm<false><<<grid, NTHREADS>>>(user_emb, item_emb, uid, pref);
    k_pos<<<B_SZ, 64>>>(seq, pref);
    if (loss_ptr) k_fin<<<1, 1>>>(loss_ptr);
}

// round 14
// speedup vs baseline: 1.0019x; 1.0019x over previous
#include <cuda_runtime.h>

#define B_SZ     1024
#define CH       64
#define NI       100000
#define HIST     50
#define BM       64
#define BN       128
#define NTHREADS 128

__device__ double g_loss;

__global__ void k_zero() { g_loss = 0.0; }

// C[b, n] = sum_k U[uid[b], k] * I[n, k]; fused sum of squares into g_loss.
template<bool ALIGNED>
__global__ __launch_bounds__(NTHREADS)
void k_gemm(const float* __restrict__ user_emb,
            const float* __restrict__ item_emb,
            const int*   __restrict__ uid,
            float*       __restrict__ pref)
{
    __shared__ float Us[CH][BM];   // 16 KB, k-major user tile
    __shared__ float Is[CH][BN];   // 32 KB, k-major item tile (total = 48 KB exactly)

    const int t  = threadIdx.x;
    const int tx = t & 15;         // 0..15 -> 8 cols each
    const int ty = t >> 4;         // 0..7  -> 8 rows each
    const int brow = blockIdx.y * BM;
    const int bcol = blockIdx.x * BN;

    // ---- load user tile (gather rows via uid), store transposed (k-major) ----
    #pragma unroll
    for (int it = 0; it < (BM * CH / 4) / NTHREADS; it++) {   // 8 iters
        int f = t + it * NTHREADS;       // float4 id
        int m = f >> 4;                  // 0..63
        int q = f & 15;                  // float4 within the 64-float row
        int u = __ldg(&uid[brow + m]);
        float4 v = *reinterpret_cast<const float4*>(user_emb + (size_t)u * CH + q * 4);
        Us[q * 4 + 0][m] = v.x;
        Us[q * 4 + 1][m] = v.y;
        Us[q * 4 + 2][m] = v.z;
        Us[q * 4 + 3][m] = v.w;
    }
    // ---- load item tile, store transposed (k-major); zero-fill past NI ----
    #pragma unroll
    for (int it = 0; it < (BN * CH / 4) / NTHREADS; it++) {   // 16 iters
        int f = t + it * NTHREADS;
        int n = f >> 4;                  // 0..127
        int q = f & 15;
        int col = bcol + n;
        float4 v = make_float4(0.f, 0.f, 0.f, 0.f);
        if (col < NI)
            v = *reinterpret_cast<const float4*>(item_emb + (size_t)col * CH + q * 4);
        Is[q * 4 + 0][n] = v.x;
        Is[q * 4 + 1][n] = v.y;
        Is[q * 4 + 2][n] = v.z;
        Is[q * 4 + 3][n] = v.w;
    }
    __syncthreads();

    float acc[8][8];
    #pragma unroll
    for (int i = 0; i < 8; i++)
        #pragma unroll
        for (int j = 0; j < 8; j++) acc[i][j] = 0.f;

    // ---- main K loop: conflict-free float4 smem reads, 64 FFMA per k ----
    #pragma unroll 8
    for (int k = 0; k < CH; k++) {
        float4 a0 = *reinterpret_cast<const float4*>(&Us[k][ty * 8]);
        float4 a1 = *reinterpret_cast<const float4*>(&Us[k][ty * 8 + 4]);
        float4 b0 = *reinterpret_cast<const float4*>(&Is[k][tx * 8]);
        float4 b1 = *reinterpret_cast<const float4*>(&Is[k][tx * 8 + 4]);
        float a[8] = {a0.x, a0.y, a0.z, a0.w, a1.x, a1.y, a1.z, a1.w};
        float b[8] = {b0.x, b0.y, b0.z, b0.w, b1.x, b1.y, b1.z, b1.w};
        #pragma unroll
        for (int i = 0; i < 8; i++)
            #pragma unroll
            for (int j = 0; j < 8; j++)
                acc[i][j] = fmaf(a[i], b[j], acc[i][j]);
    }

    // ---- fused loss partial: sum of squares (zero-padded cols contribute 0) ----
    float ls = 0.f;
    #pragma unroll
    for (int i = 0; i < 8; i++)
        #pragma unroll
        for (int j = 0; j < 8; j++)
            ls = fmaf(acc[i][j], acc[i][j], ls);
    #pragma unroll
    for (int o = 16; o > 0; o >>= 1)
        ls += __shfl_xor_sync(0xffffffffu, ls, o);

    __syncthreads();   // everyone done reading Us/Is -> safe to reuse smem

    float* red = &Us[0][0];
    if ((t & 31) == 0) red[t >> 5] = ls;

    if (ALIGNED) {
        // direct vectorized stores (pref 16B-aligned)
        #pragma unroll
        for (int i = 0; i < 8; i++) {
            int row = brow + ty * 8 + i;
            int col = bcol + tx * 8;
            if (col < NI) {   // NI % 8 == 0 so whole 8-group is valid together
                float* p = pref + (size_t)row * NI + col;
                *reinterpret_cast<float4*>(p)     = make_float4(acc[i][0], acc[i][1], acc[i][2], acc[i][3]);
                *reinterpret_cast<float4*>(p + 4) = make_float4(acc[i][4], acc[i][5], acc[i][6], acc[i][7]);
            }
        }
        __syncthreads();
        if (t == 0) atomicAdd(&g_loss, (double)(red[0] + red[1] + red[2] + red[3]));
    } else {
        // pref is off-by-one-float (loss at d_out[0]) -> stage tile in smem,
        // then coalesced scalar stores.
        float* stage = &Is[0][0];            // 64*128 floats = 32 KB
        #pragma unroll
        for (int i = 0; i < 8; i++) {
            float* s = &stage[(ty * 8 + i) * BN + tx * 8];
            *reinterpret_cast<float4*>(s)     = make_float4(acc[i][0], acc[i][1], acc[i][2], acc[i][3]);
            *reinterpret_cast<float4*>(s + 4) = make_float4(acc[i][4], acc[i][5], acc[i][6], acc[i][7]);
        }
        __syncthreads();
        if (t == 0) atomicAdd(&g_loss, (double)(red[0] + red[1] + red[2] + red[3]));
        #pragma unroll 4
        for (int idx = t; idx < BM * BN; idx += NTHREADS) {
            int r = idx >> 7;          // / BN
            int c = idx & (BN - 1);
            int col = bcol + c;
            if (col < NI)
                pref[(size_t)(brow + r) * NI + col] = stage[idx];
        }
    }
}

// Positive-mask correction: loss += sum over UNIQUE (row, seq[row][j]) of (1 - 2*s).
// Dedup matches jnp mask-scatter semantics (duplicates set the same bit once).
__global__ void k_pos(const int* __restrict__ seq, const float* __restrict__ pref)
{
    __shared__ int   s[HIST];
    __shared__ float ws[2];
    const int row = blockIdx.x;
    const int t   = threadIdx.x;     // 64 threads
    if (t < HIST) s[t] = seq[row * HIST + t];
    __syncthreads();

    float c = 0.f;
    if (t < HIST) {
        int v = s[t];
        bool dup = false;
        for (int j = 0; j < t; j++) dup |= (s[j] == v);
        if (!dup)
            c = 1.0f - 2.0f * pref[(size_t)row * NI + v];
    }
    #pragma unroll
    for (int o = 16; o > 0; o >>= 1)
        c += __shfl_xor_sync(0xffffffffu, c, o);
    if ((t & 31) == 0) ws[t >> 5] = c;
    __syncthreads();
    if (t == 0) atomicAdd(&g_loss, (double)(ws[0] + ws[1]));
}

__global__ void k_fin(float* loss_out) { *loss_out = (float)g_loss; }

extern "C" void kernel_launch(void* const* d_in, const int* in_sizes, int n_in,
                              void* d_out, int out_size)
{
    const float* user_emb = (const float*)d_in[0];
    const float* item_emb = (const float*)d_in[1];
    const int*   uid      = (const int*)d_in[2];
    const int*   seq      = (const int*)d_in[3];
    float* out = (float*)d_out;

    const long long full = (long long)B_SZ * NI;   // 102,400,000
    float* pref;
    float* loss_ptr = nullptr;
    bool aligned;

    if ((long long)out_size == full + 1) {
        // tuple order (loss, pref_score): scalar first, matrix after.
        loss_ptr = out;
        pref     = out + 1;
        aligned  = false;
    } else {
        pref    = out;
        aligned = true;
        if ((long long)out_size >= full + 1) loss_ptr = out + full;
    }

    dim3 grid((NI + BN - 1) / BN, B_SZ / BM);   // 782 x 16
    k_zero<<<1, 1>>>();
    if (aligned) k_gemm<true ><<<grid, NTHREADS>>>(user_emb, item_emb, uid, pref);
    else         k_gemm<false><<<grid, NTHREADS>>>(user_emb, item_emb, uid, pref);
    k_pos<<<B_SZ, 64>>>(seq, pref);
    if (loss_ptr) k_fin<<<1, 1>>>(loss_ptr);
}

// round 15
// speedup vs baseline: 1.0021x; 1.0002x over previous
#include <cuda_runtime.h>

#define B_SZ     1024
#define CH       64
#define NI       100000
#define HIST     50
#define BM       64
#define BN       128
#define NTHREADS 128

__device__ double g_loss;

__global__ void k_zero() { g_loss = 0.0; }

// C[b, n] = sum_k U[uid[b], k] * I[n, k]; fused sum of squares into g_loss.
template<bool ALIGNED>
__global__ __launch_bounds__(NTHREADS)
void k_gemm(const float* __restrict__ user_emb,
            const float* __restrict__ item_emb,
            const int*   __restrict__ uid,
            float*       __restrict__ pref)
{
    __shared__ float Us[CH][BM];   // 16 KB, k-major user tile
    __shared__ float Is[CH][BN];   // 32 KB, k-major item tile (total = 48 KB exactly)

    const int t  = threadIdx.x;
    const int tx = t & 15;         // 0..15 -> 8 cols each
    const int ty = t >> 4;         // 0..7  -> 8 rows each
    const int brow = blockIdx.y * BM;
    const int bcol = blockIdx.x * BN;

    // ---- load user tile (gather rows via uid), store transposed (k-major) ----
    #pragma unroll
    for (int it = 0; it < (BM * CH / 4) / NTHREADS; it++) {   // 8 iters
        int f = t + it * NTHREADS;       // float4 id
        int m = f >> 4;                  // 0..63
        int q = f & 15;                  // float4 within the 64-float row
        int u = __ldg(&uid[brow + m]);
        float4 v = *reinterpret_cast<const float4*>(user_emb + (size_t)u * CH + q * 4);
        Us[q * 4 + 0][m] = v.x;
        Us[q * 4 + 1][m] = v.y;
        Us[q * 4 + 2][m] = v.z;
        Us[q * 4 + 3][m] = v.w;
    }
    // ---- load item tile, store transposed (k-major); zero-fill past NI ----
    #pragma unroll
    for (int it = 0; it < (BN * CH / 4) / NTHREADS; it++) {   // 16 iters
        int f = t + it * NTHREADS;
        int n = f >> 4;                  // 0..127
        int q = f & 15;
        int col = bcol + n;
        float4 v = make_float4(0.f, 0.f, 0.f, 0.f);
        if (col < NI)
            v = *reinterpret_cast<const float4*>(item_emb + (size_t)col * CH + q * 4);
        Is[q * 4 + 0][n] = v.x;
        Is[q * 4 + 1][n] = v.y;
        Is[q * 4 + 2][n] = v.z;
        Is[q * 4 + 3][n] = v.w;
    }
    __syncthreads();

    float acc[8][8];
    #pragma unroll
    for (int i = 0; i < 8; i++)
        #pragma unroll
        for (int j = 0; j < 8; j++) acc[i][j] = 0.f;

    // ---- main K loop: conflict-free float4 smem reads, 64 FFMA per k ----
    #pragma unroll 8
    for (int k = 0; k < CH; k++) {
        float4 a0 = *reinterpret_cast<const float4*>(&Us[k][ty * 8]);
        float4 a1 = *reinterpret_cast<const float4*>(&Us[k][ty * 8 + 4]);
        float4 b0 = *reinterpret_cast<const float4*>(&Is[k][tx * 8]);
        float4 b1 = *reinterpret_cast<const float4*>(&Is[k][tx * 8 + 4]);
        float a[8] = {a0.x, a0.y, a0.z, a0.w, a1.x, a1.y, a1.z, a1.w};
        float b[8] = {b0.x, b0.y, b0.z, b0.w, b1.x, b1.y, b1.z, b1.w};
        #pragma unroll
        for (int i = 0; i < 8; i++)
            #pragma unroll
            for (int j = 0; j < 8; j++)
                acc[i][j] = fmaf(a[i], b[j], acc[i][j]);
    }

    // ---- fused loss partial: sum of squares (zero-padded cols contribute 0) ----
    float ls = 0.f;
    #pragma unroll
    for (int i = 0; i < 8; i++)
        #pragma unroll
        for (int j = 0; j < 8; j++)
            ls = fmaf(acc[i][j], acc[i][j], ls);
    #pragma unroll
    for (int o = 16; o > 0; o >>= 1)
        ls += __shfl_xor_sync(0xffffffffu, ls, o);

    __syncthreads();   // everyone done reading Us/Is -> safe to reuse smem

    float* red = &Us[0][0];
    if ((t & 31) == 0) red[t >> 5] = ls;

    if (ALIGNED) {
        // direct vectorized stores (pref 16B-aligned)
        #pragma unroll
        for (int i = 0; i < 8; i++) {
            int row = brow + ty * 8 + i;
            int col = bcol + tx * 8;
            if (col < NI) {   // NI % 8 == 0 so whole 8-group is valid together
                float* p = pref + (size_t)row * NI + col;
                *reinterpret_cast<float4*>(p)     = make_float4(acc[i][0], acc[i][1], acc[i][2], acc[i][3]);
                *reinterpret_cast<float4*>(p + 4) = make_float4(acc[i][4], acc[i][5], acc[i][6], acc[i][7]);
            }
        }
        __syncthreads();
        if (t == 0) atomicAdd(&g_loss, (double)(red[0] + red[1] + red[2] + red[3]));
    } else {
        // pref is off-by-one-float (loss at d_out[0]) -> stage tile in smem,
        // then coalesced scalar stores.
        float* stage = &Is[0][0];            // 64*128 floats = 32 KB
        #pragma unroll
        for (int i = 0; i < 8; i++) {
            float* s = &stage[(ty * 8 + i) * BN + tx * 8];
            *reinterpret_cast<float4*>(s)     = make_float4(acc[i][0], acc[i][1], acc[i][2], acc[i][3]);
            *reinterpret_cast<float4*>(s + 4) = make_float4(acc[i][4], acc[i][5], acc[i][6], acc[i][7]);
        }
        __syncthreads();
        if (t == 0) atomicAdd(&g_loss, (double)(red[0] + red[1] + red[2] + red[3]));
        #pragma unroll 4
        for (int idx = t; idx < BM * BN; idx += NTHREADS) {
            int r = idx >> 7;          // / BN
            int c = idx & (BN - 1);
            int col = bcol + c;
            if (col < NI)
                pref[(size_t)(brow + r) * NI + col] = stage[idx];
        }
    }
}

// Positive-mask correction: loss += sum over UNIQUE (row, seq[row][j]) of (1 - 2*s).
// Dedup matches jnp mask-scatter semantics (duplicates set the same bit once).
__global__ void k_pos(const int* __restrict__ seq, const float* __restrict__ pref)
{
    __shared__ int   s[HIST];
    __shared__ float ws[2];
    const int row = blockIdx.x;
    const int t   = threadIdx.x;     // 64 threads
    if (t < HIST) s[t] = seq[row * HIST + t];
    __syncthreads();

    float c = 0.f;
    if (t < HIST) {
        int v = s[t];
        bool dup = false;
        for (int j = 0; j < t; j++) dup |= (s[j] == v);
        if (!dup)
            c = 1.0f - 2.0f * pref[(size_t)row * NI + v];
    }
    #pragma unroll
    for (int o = 16; o > 0; o >>= 1)
        c += __shfl_xor_sync(0xffffffffu, c, o);
    if ((t & 31) == 0) ws[t >> 5] = c;
    __syncthreads();
    if (t == 0) atomicAdd(&g_loss, (double)(ws[0] + ws[1]));
}

__global__ void k_fin(float* loss_out) { *loss_out = (float)g_loss; }

extern "C" void kernel_launch(void* const* d_in, const int* in_sizes, int n_in,
                              void* d_out, int out_size)
{
    const float* user_emb = (const float*)d_in[0];
    const float* item_emb = (const float*)d_in[1];
    const int*   uid      = (const int*)d_in[2];
    const int*   seq      = (const int*)d_in[3];
    float* out = (float*)d_out;

    const long long full = (long long)B_SZ * NI;   // 102,400,000
    float* pref;
    float* loss_ptr = nullptr;
    bool aligned;

    if ((long long)out_size == full + 1) {
        // tuple order (loss, pref_score): scalar first, matrix after.
        loss_ptr = out;
        pref     = out + 1;
        aligned  = false;
    } else {
        pref    = out;
        aligned = true;
        if ((long long)out_size >= full + 1) loss_ptr = out + full;
    }

    dim3 grid((NI + BN - 1) / BN, B_SZ / BM);   // 782 x 16
    k_zero<<<1, 1>>>();
    if (aligned) k_gemm<true ><<<grid, NTHREADS>>>(user_emb, item_emb, uid, pref);
    else         k_gemm<false><<<grid, NTHREADS>>>(user_emb, item_emb, uid, pref);
    k_pos<<<B_SZ, 64>>>(seq, pref);
    if (loss_ptr) k_fin<<<1, 1>>>(loss_ptr);
}

// round 17
// speedup vs baseline: 2.0448x; 2.0405x over previous
#include <cuda_runtime.h>
#include <cuda_bf16.h>
#include <cstdint>

#define B_SZ 1024
#define CH   64
#define NI   100000
#define HIST 50
#define KE   192            // extended K: A=[hi|lo|hi], B=[hi|hi|lo]
#define TM   128
#define TN   128
#define NTHR 256

__device__ double g_loss;
__device__ __align__(16) __nv_bfloat16 g_item_ext[(size_t)NI * KE];
__device__ __align__(16) __nv_bfloat16 g_user_ext[(size_t)B_SZ * KE];

__global__ void k_zero() { g_loss = 0.0; }

// ---------------- prep: fp32 -> bf16 hi/lo extended-K layouts ----------------
__global__ void k_prep_item(const float* __restrict__ it)
{
    int tid = blockIdx.x * blockDim.x + threadIdx.x;
    if (tid >= NI * 16) return;
    int r = tid >> 4, q = tid & 15;
    float4 v = *reinterpret_cast<const float4*>(it + (size_t)r * CH + q * 4);
    float f[4] = {v.x, v.y, v.z, v.w};
    __nv_bfloat16* base = g_item_ext + (size_t)r * KE + q * 4;
    #pragma unroll
    for (int i = 0; i < 4; i++) {
        __nv_bfloat16 hi = __float2bfloat16(f[i]);
        __nv_bfloat16 lo = __float2bfloat16(f[i] - __bfloat162float(hi));
        base[i]       = hi;   // B' cols [0,64)   : hi
        base[64 + i]  = hi;   // B' cols [64,128) : hi
        base[128 + i] = lo;   // B' cols [128,192): lo
    }
}

__global__ void k_prep_user(const float* __restrict__ ue, const int* __restrict__ uid)
{
    int tid = blockIdx.x * blockDim.x + threadIdx.x;
    if (tid >= B_SZ * 16) return;
    int r = tid >> 4, q = tid & 15;
    int u = __ldg(&uid[r]);
    float4 v = *reinterpret_cast<const float4*>(ue + (size_t)u * CH + q * 4);
    float f[4] = {v.x, v.y, v.z, v.w};
    __nv_bfloat16* base = g_user_ext + (size_t)r * KE + q * 4;
    #pragma unroll
    for (int i = 0; i < 4; i++) {
        __nv_bfloat16 hi = __float2bfloat16(f[i]);
        __nv_bfloat16 lo = __float2bfloat16(f[i] - __bfloat162float(hi));
        base[i]       = hi;   // A' cols [0,64)   : hi
        base[64 + i]  = lo;   // A' cols [64,128) : lo
        base[128 + i] = hi;   // A' cols [128,192): hi
    }
}

// ---------------- helpers ----------------
__device__ __forceinline__ uint32_t smem_u32(const void* p) {
    uint32_t a;
    asm("{ .reg .u64 t; cvta.to.shared.u64 t, %1; cvt.u32.u64 %0, t; }" : "=r"(a) : "l"(p));
    return a;
}
__device__ __forceinline__ uint32_t sw128(uint32_t b) { return b ^ ((b >> 3) & 0x70); }

// blocked-atom K-major SW128 tile: rows in 8-row atoms, k in 64-elem chunks
__device__ __forceinline__ uint32_t tile_off(int r, int k) {
    return (uint32_t)((((k >> 6) * 16 + (r >> 3)) << 10) + ((r & 7) << 7) + ((k & 63) << 1));
}

__device__ __forceinline__ void ldsm_x4(uint32_t* d, uint32_t addr) {
    asm volatile("ldmatrix.sync.aligned.m8n8.x4.shared.b16 {%0,%1,%2,%3}, [%4];"
                 : "=r"(d[0]), "=r"(d[1]), "=r"(d[2]), "=r"(d[3]) : "r"(addr));
}

__device__ __forceinline__ void mma16816(float* c, const uint32_t* a, uint32_t b0, uint32_t b1) {
    asm volatile(
        "mma.sync.aligned.m16n8k16.row.col.f32.bf16.bf16.f32 "
        "{%0,%1,%2,%3}, {%4,%5,%6,%7}, {%8,%9}, {%0,%1,%2,%3};"
        : "+f"(c[0]), "+f"(c[1]), "+f"(c[2]), "+f"(c[3])
        : "r"(a[0]), "r"(a[1]), "r"(a[2]), "r"(a[3]), "r"(b0), "r"(b1));
}

// ---------------- GEMM: C[1024,100000] via mma.sync bf16 split-K192 ----------------
// dyn smem (1024-aligned): [0,48K) A' tile, [48K,96K) B' tile; stage 128x129 fp32
// reuses [0,66K) after compute; misc at 96K.
#define A_OFF   0
#define B_OFF   (48 * 1024)
#define MISC    (96 * 1024)
#define DSMEM   (96 * 1024 + 64 + 1024)

__global__ __launch_bounds__(NTHR, 2)
void k_gemm_hmma(float* __restrict__ pref)
{
    extern __shared__ char dsm_raw[];
    uint32_t raw  = smem_u32(dsm_raw);
    uint32_t base = (raw + 1023u) & ~1023u;
    char* dsm = dsm_raw + (base - raw);

    const int t    = threadIdx.x;
    const int w    = t >> 5;
    const int lane = t & 31;
    const int wm   = w >> 2;          // 0..1  -> 64-row slab
    const int wn   = w & 3;           // 0..3  -> 32-col slab
    const int brow = blockIdx.x * TM; // grid.x = 8 (M)
    const int bcol = blockIdx.y * TN; // grid.y = 782 (N)

    // ---- fill A' tile (128 x 192 bf16, blocked-atom SW128) ----
    #pragma unroll
    for (int c = 0; c < 3; c++)
        #pragma unroll
        for (int j = 0; j < 4; j++) {
            int idx = j * NTHR + t;            // 0..1023
            int r = idx >> 3, q = idx & 7;
            int k = c * 64 + q * 8;
            uint4 v = *reinterpret_cast<const uint4*>(g_user_ext + (size_t)(brow + r) * KE + k);
            *reinterpret_cast<uint4*>(dsm + A_OFF + sw128(tile_off(r, k))) = v;
        }
    // ---- fill B' tile (128 items x 192 bf16), zero-fill OOB items ----
    #pragma unroll
    for (int c = 0; c < 3; c++)
        #pragma unroll
        for (int j = 0; j < 4; j++) {
            int idx = j * NTHR + t;
            int r = idx >> 3, q = idx & 7;
            int k = c * 64 + q * 8;
            uint4 v = make_uint4(0u, 0u, 0u, 0u);
            if (bcol + r < NI)
                v = *reinterpret_cast<const uint4*>(g_item_ext + (size_t)(bcol + r) * KE + k);
            *reinterpret_cast<uint4*>(dsm + B_OFF + sw128(tile_off(r, k))) = v;
        }
    __syncthreads();

    // ---- warp-tile 64x32: 4 m-atoms x 4 n-atoms, 12 K-steps of 16 ----
    float acc[4][4][4];
    #pragma unroll
    for (int i = 0; i < 4; i++)
        #pragma unroll
        for (int j = 0; j < 4; j++)
            #pragma unroll
            for (int q = 0; q < 4; q++) acc[i][j][q] = 0.f;

    const int lr = lane & 15;         // row within 16-row fragment
    const int lh = lane >> 4;         // k-half selector (0/1 -> k+0/k+8)
    const uint32_t abase = base + A_OFF;
    const uint32_t bbase = base + B_OFF;

    #pragma unroll
    for (int s = 0; s < 12; s++) {
        const int kb = s * 16 + lh * 8;
        uint32_t af[4][4];
        #pragma unroll
        for (int mi = 0; mi < 4; mi++)
            ldsm_x4(af[mi], abase + sw128(tile_off(wm * 64 + mi * 16 + lr, kb)));
        uint32_t bf[2][4];
        #pragma unroll
        for (int p = 0; p < 2; p++)
            ldsm_x4(bf[p], bbase + sw128(tile_off(wn * 32 + p * 16 + lr, kb)));
        #pragma unroll
        for (int mi = 0; mi < 4; mi++)
            #pragma unroll
            for (int nj = 0; nj < 4; nj++) {
                const int p = nj >> 1, o = nj & 1;
                mma16816(acc[mi][nj], af[mi], bf[p][o], bf[p][o + 2]);
            }
    }
    __syncthreads();   // tiles fully consumed -> reuse smem as stage

    // ---- epilogue: fragments -> stage smem (pitch 129) + fused loss ----
    float* stage = reinterpret_cast<float*>(dsm);
    const int g  = lane >> 2;
    const int c2 = (lane & 3) * 2;
    float lsum = 0.f;
    #pragma unroll
    for (int mi = 0; mi < 4; mi++)
        #pragma unroll
        for (int nj = 0; nj < 4; nj++) {
            const int r0  = wm * 64 + mi * 16 + g;
            const int col = wn * 32 + nj * 8 + c2;
            float v0 = acc[mi][nj][0], v1 = acc[mi][nj][1];
            float v2 = acc[mi][nj][2], v3 = acc[mi][nj][3];
            stage[r0 * 129 + col]           = v0;
            stage[r0 * 129 + col + 1]       = v1;
            stage[(r0 + 8) * 129 + col]     = v2;
            stage[(r0 + 8) * 129 + col + 1] = v3;
            lsum = fmaf(v0, v0, lsum);
            lsum = fmaf(v1, v1, lsum);
            lsum = fmaf(v2, v2, lsum);
            lsum = fmaf(v3, v3, lsum);
        }
    #pragma unroll
    for (int o = 16; o > 0; o >>= 1)
        lsum += __shfl_xor_sync(0xffffffffu, lsum, o);
    float* red = reinterpret_cast<float*>(dsm + MISC);
    if (lane == 0) red[w] = lsum;
    __syncthreads();
    if (t == 0) {
        float s = 0.f;
        #pragma unroll
        for (int i = 0; i < 8; i++) s += red[i];
        atomicAdd(&g_loss, (double)s);
    }

    // ---- coalesced stores; alignment-shift handles pref = out+1 ----
    const int ncols = min(TN, NI - bcol);
    const int s0 = (int)((4u - ((((uintptr_t)pref) >> 2) & 3u)) & 3u);
    const int Vr = (ncols > s0) ? ((ncols - s0) >> 2) : 0;
    const int tailc = ncols - s0 - 4 * Vr;
    const int nsc = s0 + tailc;

    for (int rr = w; rr < TM; rr += 8) {
        const float* srow = stage + rr * 129;
        size_t gbase = (size_t)(brow + rr) * NI + bcol;
        if (lane < Vr) {
            int col = s0 + 4 * lane;
            float4 v = make_float4(srow[col], srow[col + 1], srow[col + 2], srow[col + 3]);
            *reinterpret_cast<float4*>(pref + gbase + col) = v;
        }
        if (lane < nsc) {
            int col = (lane < s0) ? lane : s0 + 4 * Vr + (lane - s0);
            pref[gbase + col] = srow[col];
        }
    }
}

// ---------------- positive-mask correction (dedup) ----------------
__global__ void k_pos(const int* __restrict__ seq, const float* __restrict__ pref)
{
    __shared__ int   s[HIST];
    __shared__ float ws[2];
    const int row = blockIdx.x;
    const int t   = threadIdx.x;
    if (t < HIST) s[t] = seq[row * HIST + t];
    __syncthreads();

    float c = 0.f;
    if (t < HIST) {
        int v = s[t];
        bool dup = false;
        for (int j = 0; j < t; j++) dup |= (s[j] == v);
        if (!dup)
            c = 1.0f - 2.0f * pref[(size_t)row * NI + v];
    }
    #pragma unroll
    for (int o = 16; o > 0; o >>= 1)
        c += __shfl_xor_sync(0xffffffffu, c, o);
    if ((t & 31) == 0) ws[t >> 5] = c;
    __syncthreads();
    if (t == 0) atomicAdd(&g_loss, (double)(ws[0] + ws[1]));
}

__global__ void k_fin(float* loss_out) { *loss_out = (float)g_loss; }

extern "C" void kernel_launch(void* const* d_in, const int* in_sizes, int n_in,
                              void* d_out, int out_size)
{
    const float* user_emb = (const float*)d_in[0];
    const float* item_emb = (const float*)d_in[1];
    const int*   uid      = (const int*)d_in[2];
    const int*   seq      = (const int*)d_in[3];
    float* out = (float*)d_out;

    const long long full = (long long)B_SZ * NI;
    float* pref;
    float* loss_ptr = nullptr;
    if ((long long)out_size == full + 1) {          // tuple order (loss, pref)
        loss_ptr = out;
        pref     = out + 1;
    } else {
        pref = out;
        if ((long long)out_size >= full + 1) loss_ptr = out + full;
    }

    cudaFuncSetAttribute(k_gemm_hmma, cudaFuncAttributeMaxDynamicSharedMemorySize, DSMEM);

    k_zero<<<1, 1>>>();
    k_prep_item<<<(NI * 16 + 255) / 256, 256>>>(item_emb);
    k_prep_user<<<(B_SZ * 16 + 255) / 256, 256>>>(user_emb, uid);
    dim3 grid(B_SZ / TM, (NI + TN - 1) / TN);       // 8 x 782
    k_gemm_hmma<<<grid, NTHR, DSMEM>>>(pref);
    k_pos<<<B_SZ, 64>>>(seq, pref);
    if (loss_ptr) k_fin<<<1, 1>>>(loss_ptr);
}